// round 16
// baseline (speedup 1.0000x reference)
#include <cuda_runtime.h>
#include <cuda_fp16.h>

// ---------------- problem constants ----------------
#define NN 10000
#define LL 256
#define EE 160000
#define HH 64
#define DM 4
#define DS 32
#define DC 4
#define DI 8
#define NLAYERS 8
#define EPSV 1e-6f

// ---------------- scratch (device globals; no allocation) ----------------
__device__ float g_h[NN * HH];          // node features
__device__ float g_e[EE * HH];          // edge features (updated in place)
__device__ __half g_sig[EE * HH];       // sigmoid(e) cache (written by k_edge)
__device__ float g_hw[NN * 5 * HH];     // A1|A2|A3|B1|B2 per node (reused by pred)
__device__ __half g_hwh[NN * 128];      // fp16 copy of A2h|A3h for aggregation gathers
__device__ float g_x2[NN * DM];
__device__ int g_deg_in[NN], g_deg_out[NN];
__device__ int g_ofs_in[NN + 1], g_ofs_out[NN + 1];
__device__ int g_cur_in[NN], g_cur_out[NN];
__device__ int g_csr_in[EE], g_csr_out[EE];
__device__ int g_order[NN];

__device__ __forceinline__ float sigmoidf_(float x) {
    return 1.f / (1.f + __expf(-x));
}

// ---------------- CSR build ----------------
__global__ void k_zero_deg() {
    int i = blockIdx.x * blockDim.x + threadIdx.x;
    if (i < NN) { g_deg_in[i] = 0; g_deg_out[i] = 0; }
}

__global__ void k_hist(const int* __restrict__ src, const int* __restrict__ dst) {
    int i = blockIdx.x * blockDim.x + threadIdx.x;
    if (i < EE) {
        atomicAdd(&g_deg_in[dst[i]], 1);
        atomicAdd(&g_deg_out[src[i]], 1);
    }
}

__global__ void k_scan() {
    __shared__ int part[1024];
    int t = threadIdx.x;
    for (int pass = 0; pass < 2; pass++) {
        const int* deg = pass ? g_deg_out : g_deg_in;
        int* ofs = pass ? g_ofs_out : g_ofs_in;
        int* cur = pass ? g_cur_out : g_cur_in;
        int lo = t * 10;
        int hi = lo + 10; if (hi > NN) hi = NN;
        int s = 0;
        for (int i = lo; i < hi && i < NN; i++) s += deg[i];
        part[t] = s;
        __syncthreads();
        for (int d = 1; d < 1024; d <<= 1) {
            int add = (t >= d) ? part[t - d] : 0;
            __syncthreads();
            part[t] += add;
            __syncthreads();
        }
        int run = part[t] - s;  // exclusive base
        for (int i = lo; i < hi && i < NN; i++) {
            ofs[i] = run; cur[i] = run; run += deg[i];
        }
        if (lo < NN && hi == NN) ofs[NN] = run;
        __syncthreads();
    }
}

__global__ void k_fill(const int* __restrict__ src, const int* __restrict__ dst) {
    int i = blockIdx.x * blockDim.x + threadIdx.x;
    if (i < EE) {
        int p = atomicAdd(&g_cur_in[dst[i]], 1);
        g_csr_in[p] = i;
        int q = atomicAdd(&g_cur_out[src[i]], 1);
        g_csr_out[q] = i;
    }
}

// deterministic order: warp-bitonic sort of each node's edge-id segment (len<=64 fast path)
__global__ void k_sortcsr() {
    int gw = (blockIdx.x * blockDim.x + threadIdx.x) >> 5;
    int lane = threadIdx.x & 31;
    if (gw >= 2 * NN) return;
    int n = (gw < NN) ? gw : gw - NN;
    int* csr = (gw < NN) ? g_csr_in : g_csr_out;
    const int* ofs = (gw < NN) ? g_ofs_in : g_ofs_out;
    int beg = ofs[n], end = ofs[n + 1];
    int len = end - beg;
    if (len <= 1) return;
    if (len <= 64) {
        const int INF = 0x7fffffff;
        int a = (lane < len) ? csr[beg + lane] : INF;
        int b = (32 + lane < len) ? csr[beg + 32 + lane] : INF;
#pragma unroll
        for (int k = 2; k <= 64; k <<= 1) {
#pragma unroll
            for (int j = 32; j > 0; j >>= 1) {
                if (j >= k) continue;
                if (j == 32) {
                    int lo = min(a, b), hi = max(a, b);
                    a = lo; b = hi;
                } else {
                    int pa = __shfl_xor_sync(0xffffffffu, a, j);
                    bool upa = ((lane & j) == 0);
                    bool asca = ((lane & k) == 0);
                    a = (upa == asca) ? min(a, pa) : max(a, pa);
                    int pb = __shfl_xor_sync(0xffffffffu, b, j);
                    int idxb = lane + 32;
                    bool upb = ((idxb & j) == 0);
                    bool ascb = ((idxb & k) == 0);
                    b = (upb == ascb) ? min(b, pb) : max(b, pb);
                }
            }
        }
        if (lane < len) csr[beg + lane] = a;
        if (32 + lane < len) csr[beg + 32 + lane] = b;
    } else {
        if (lane == 0) {
            for (int i = beg + 1; i < end; i++) {
                int key = csr[i]; int j = i - 1;
                while (j >= beg && csr[j] > key) { csr[j + 1] = csr[j]; j--; }
                csr[j + 1] = key;
            }
        }
    }
}

// ---------------- read_length binning: fused hist+scan+place, descending rl (LPT) ----------------
__global__ void k_rlscanplace(const int* __restrict__ rl) {
    __shared__ int sbin[LL];
    __shared__ int sofs[LL];
    int t = threadIdx.x;  // 256
    sbin[t] = 0;
    __syncthreads();
    for (int i = t; i < NN; i += 256) atomicAdd(&sbin[rl[i] - 1], 1);
    __syncthreads();
    int v = sbin[t];
    for (int d = 1; d < LL; d <<= 1) {
        int add = (t >= d) ? sbin[t - d] : 0;
        __syncthreads();
        sbin[t] += add;
        __syncthreads();
    }
    sofs[t] = sbin[t] - v;  // exclusive (ascending)
    __syncthreads();
    for (int i = t; i < NN; i += 256) {
        int pos = atomicAdd(&sofs[rl[i] - 1], 1);
        g_order[NN - 1 - pos] = i;   // descending rl -> LPT scheduling
    }
}

// ---------------- mamba: warp per node (rl-sorted desc), lane = state index ----------------
__global__ void k_mamba(const float* __restrict__ reads, const int* __restrict__ read_length,
                        const float* __restrict__ in_proj_W, const float* __restrict__ conv_W,
                        const float* __restrict__ conv_b, const float* __restrict__ x_proj_W,
                        const float* __restrict__ dt_proj_W, const float* __restrict__ dt_proj_b,
                        const float* __restrict__ A_log, const float* __restrict__ Dskip,
                        const float* __restrict__ out_proj_W) {
    __shared__ float op[32];
    __shared__ float ys[8][8], os[8][8];
    int tid = threadIdx.x;
    if (tid < 32) op[tid] = out_proj_W[tid];
    __syncthreads();
    int warp = tid >> 5, lane = tid & 31;
    int idx = blockIdx.x * 8 + warp;
    if (idx >= NN) return;
    int li = lane & 7;

    float ipx[4], ipz[4], cwr[4];
#pragma unroll
    for (int m = 0; m < 4; m++) {
        ipx[m] = __ldg(&in_proj_W[m * 16 + li]);
        ipz[m] = __ldg(&in_proj_W[m * 16 + 8 + li]);
        cwr[m] = __ldg(&conv_W[li * 4 + m]);
    }
    float cbr = __ldg(&conv_b[li]);
    float dtwr = __ldg(&dt_proj_W[li]);
    float dtbr = __ldg(&dt_proj_b[li]);
    float dskr = __ldg(&Dskip[li]);
    float xp0r[8], xpBr[8], xpCr[8], Asr[8];
#pragma unroll
    for (int i = 0; i < 8; i++) {
        xp0r[i] = __ldg(&x_proj_W[i * 65]);
        xpBr[i] = __ldg(&x_proj_W[i * 65 + 1 + lane]);
        xpCr[i] = __ldg(&x_proj_W[i * 65 + 33 + lane]);
        Asr[i] = -__expf(__ldg(&A_log[i * 32 + lane]));
    }

    int n = g_order[idx];
    int rl = read_length[n];
    float hst[8];
#pragma unroll
    for (int i = 0; i < 8; i++) hst[i] = 0.f;
    float c0 = 0.f, c1 = 0.f, c2 = 0.f;
    float xc = 0.f, zf = 0.f, CsLast = 0.f;
    const float4* rd4 = (const float4*)(reads + (size_t)n * LL * 4);
    float4 rd = rd4[0];

    for (int t = 0; t < rl; t++) {
        int tn = (t + 1 < rl) ? (t + 1) : t;
        float4 nxt = rd4[tn];                          // prefetch
        float xh = rd.x * ipx[0] + rd.y * ipx[1] + rd.z * ipx[2] + rd.w * ipx[3];
        float c = c0 * cwr[0] + c1 * cwr[1] + c2 * cwr[2] + xh * cwr[3] + cbr;
        c0 = c1; c1 = c2; c2 = xh;
        xc = c * sigmoidf_(c);
        if (t == rl - 1)
            zf = rd.x * ipz[0] + rd.y * ipz[1] + rd.z * ipz[2] + rd.w * ipz[3];

        float xr[8];
        float dbl0 = 0.f, Bs = 0.f, Cs = 0.f;
#pragma unroll
        for (int i = 0; i < 8; i++) {
            float xi = __shfl_sync(0xffffffffu, xc, i);
            xr[i] = xi;
            dbl0 += xi * xp0r[i];
            Bs += xi * xpBr[i];
            Cs += xi * xpCr[i];
        }
        float dr = dbl0 * dtwr + dtbr;
        float dtv = (dr > 15.f) ? dr : __logf(1.f + __expf(dr));
#pragma unroll
        for (int i = 0; i < 8; i++) {
            float dti = __shfl_sync(0xffffffffu, dtv, i);
            hst[i] = __expf(dti * Asr[i]) * hst[i] + (dti * Bs) * xr[i];
        }
        if (t == rl - 1) CsLast = Cs;
        rd = nxt;
    }
#pragma unroll
    for (int i = 0; i < 8; i++) {
        float v = hst[i] * CsLast;
#pragma unroll
        for (int off = 16; off; off >>= 1) v += __shfl_xor_sync(0xffffffffu, v, off);
        if (lane == 0) ys[warp][i] = v;
    }
    __syncwarp();
    if (lane < 8) {
        float y = ys[warp][lane] + xc * dskr;
        os[warp][lane] = y * (zf * sigmoidf_(zf));
    }
    __syncwarp();
    if (lane < 4) {
        float acc = 0.f;
#pragma unroll
        for (int i = 0; i < 8; i++) acc += os[warp][i] * op[i * 4 + lane];
        g_x2[n * 4 + lane] = acc;
    }
}

// ---------------- encoders ----------------
__global__ void k_enc(const float* __restrict__ in, const float* __restrict__ W1,
                      const float* __restrict__ b1, const float* __restrict__ W2,
                      const float* __restrict__ b2, int rows, int target_e) {
    float* outp = target_e ? g_e : g_h;
    int tid = threadIdx.x;
    int j = tid & 63, g = tid >> 6;
    float w1a[16], w1b[16], bb1[16], w2c[16];
#pragma unroll
    for (int i = 0; i < 16; i++) {
        w1a[i] = W1[i];
        w1b[i] = W1[16 + i];
        bb1[i] = b1[i];
        w2c[i] = W2[i * 64 + j];
    }
    float b2j = b2[j];
    for (int r = blockIdx.x * 4 + g; r < rows; r += gridDim.x * 4) {
        float x0 = in[r * 2], x1 = in[r * 2 + 1];
        float acc = b2j;
#pragma unroll
        for (int i = 0; i < 16; i++) {
            float hid = fmaxf(x0 * w1a[i] + x1 * w1b[i] + bb1[i], 0.f);
            acc += hid * w2c[i];
        }
        outp[r * 64 + j] = acc;
    }
}

// ---------------- node GEMM (tiled): g_hw[:, m*64:(m+1)*64] = h @ W_m + b_m, m = m0 + blockIdx.y ----------------
// also writes fp16 copies of A2h (m=1) and A3h (m=2) into g_hwh for the aggregation gathers
__global__ void __launch_bounds__(256)
k_hw(const float* __restrict__ gnn_W, const float* __restrict__ gnn_b, int l, int m0) {
    __shared__ float hsT[64][68];   // hsT[k][node_local]
    __shared__ float ws[64][68];    // ws[k][c]
    int tid = threadIdx.x;
    int tx = tid & 15, ty = tid >> 4;
    int n0 = blockIdx.x * 64;
    int m = m0 + blockIdx.y;
    const float* Wm = gnn_W + (size_t)(l * 6 + m) * 4096;
#pragma unroll
    for (int i = 0; i < 16; i++) {
        int idx = tid + 256 * i;
        int rr = idx >> 6, cc = idx & 63;
        ws[rr][cc] = Wm[idx];
        int n = n0 + rr;
        hsT[cc][rr] = (n < NN) ? g_h[(size_t)n * 64 + cc] : 0.f;
    }
    __syncthreads();
    float acc[4][4] = {{0.f}};
#pragma unroll 16
    for (int k = 0; k < 64; k++) {
        float4 a = *(const float4*)&hsT[k][4 * ty];
        float4 b = *(const float4*)&ws[k][4 * tx];
        acc[0][0] += a.x * b.x; acc[0][1] += a.x * b.y; acc[0][2] += a.x * b.z; acc[0][3] += a.x * b.w;
        acc[1][0] += a.y * b.x; acc[1][1] += a.y * b.y; acc[1][2] += a.y * b.z; acc[1][3] += a.y * b.w;
        acc[2][0] += a.z * b.x; acc[2][1] += a.z * b.y; acc[2][2] += a.z * b.z; acc[2][3] += a.z * b.w;
        acc[3][0] += a.w * b.x; acc[3][1] += a.w * b.y; acc[3][2] += a.w * b.z; acc[3][3] += a.w * b.w;
    }
    const float* bm = gnn_b + (size_t)(l * 6 + m) * 64;
    float4 bias = *(const float4*)&bm[4 * tx];
#pragma unroll
    for (int i = 0; i < 4; i++) {
        int n = n0 + 4 * ty + i;
        if (n >= NN) break;
        float4 r;
        r.x = acc[i][0] + bias.x;
        r.y = acc[i][1] + bias.y;
        r.z = acc[i][2] + bias.z;
        r.w = acc[i][3] + bias.w;
        *(float4*)&g_hw[(size_t)n * 320 + m * 64 + 4 * tx] = r;
        if (m == 1 || m == 2) {   // A2h / A3h fp16 copy for k_agg
            __half2 p01 = __floats2half2_rn(r.x, r.y);
            __half2 p23 = __floats2half2_rn(r.z, r.w);
            __half2* hp = (__half2*)&g_hwh[(size_t)n * 128 + (m - 1) * 64 + 4 * tx];
            hp[0] = p01;
            hp[1] = p23;
        }
    }
}

// ---------------- per-layer edge update: 128-edge tile, thread = 8 edges x 4 channels ----------------
// grid 1250, block 256; EE = 1250*128 exactly
__global__ void __launch_bounds__(256)
k_edge(const int* __restrict__ src, const int* __restrict__ dst,
       const float* __restrict__ gnn_W, const float* __restrict__ gnn_b, int l) {
    __shared__ float es[128][64];   // es[edge][k], row-major
    __shared__ float ws[64][64];    // ws[k][c]
    __shared__ int ssrc[128], sdst[128];
    int tid = threadIdx.x;
    int tx = tid & 15, ty = tid >> 4;   // tx: channel group (4*tx), ty: edge group (8*ty)
    int e0 = blockIdx.x * 128;
    const float* W5 = gnn_W + (size_t)(l * 6 + 5) * 4096;
#pragma unroll
    for (int i = 0; i < 8; i++) {
        int idx = tid + 256 * i;            // float4 idx 0..2047
        int r4 = idx >> 4, c4 = idx & 15;
        float4 ev = *(const float4*)&g_e[(size_t)(e0 + r4) * 64 + 4 * c4];
        *(float4*)&es[r4][4 * c4] = ev;
    }
#pragma unroll
    for (int i = 0; i < 4; i++) {
        int idx = tid + 256 * i;            // float4 idx 0..1023
        int r4 = idx >> 4, c4 = idx & 15;
        float4 wv = *(const float4*)&W5[(size_t)r4 * 64 + 4 * c4];
        *(float4*)&ws[r4][4 * c4] = wv;
    }
    if (tid < 128) { ssrc[tid] = src[e0 + tid]; sdst[tid] = dst[e0 + tid]; }
    __syncthreads();
    float acc[8][4] = {{0.f}};
#pragma unroll
    for (int k4 = 0; k4 < 16; k4++) {
        int k = 4 * k4;
        float4 b0 = *(const float4*)&ws[k + 0][4 * tx];
        float4 b1 = *(const float4*)&ws[k + 1][4 * tx];
        float4 b2 = *(const float4*)&ws[k + 2][4 * tx];
        float4 b3 = *(const float4*)&ws[k + 3][4 * tx];
#pragma unroll
        for (int i = 0; i < 8; i++) {
            float4 a = *(const float4*)&es[8 * ty + i][k];
            acc[i][0] += a.x * b0.x + a.y * b1.x + a.z * b2.x + a.w * b3.x;
            acc[i][1] += a.x * b0.y + a.y * b1.y + a.z * b2.y + a.w * b3.y;
            acc[i][2] += a.x * b0.z + a.y * b1.z + a.z * b2.z + a.w * b3.z;
            acc[i][3] += a.x * b0.w + a.y * b1.w + a.z * b2.w + a.w * b3.w;
        }
    }
    const float* b5 = gnn_b + (size_t)(l * 6 + 5) * 64;
    float4 bias = *(const float4*)&b5[4 * tx];
#pragma unroll
    for (int i = 0; i < 8; i++) {
        int el = 8 * ty + i;
        int eg = e0 + el;
        int s = ssrc[el], d = sdst[el];
        float4 h1 = *(const float4*)&g_hw[(size_t)s * 320 + 192 + 4 * tx];
        float4 h2 = *(const float4*)&g_hw[(size_t)d * 320 + 256 + 4 * tx];
        float4 ea = *(const float4*)&es[el][4 * tx];
        float4 r;
        r.x = ea.x + fmaxf(acc[i][0] + bias.x + h1.x + h2.x, 0.f);
        r.y = ea.y + fmaxf(acc[i][1] + bias.y + h1.y + h2.y, 0.f);
        r.z = ea.z + fmaxf(acc[i][2] + bias.z + h1.z + h2.z, 0.f);
        r.w = ea.w + fmaxf(acc[i][3] + bias.w + h1.w + h2.w, 0.f);
        *(float4*)&g_e[(size_t)eg * 64 + 4 * tx] = r;
        __half2 s01 = __floats2half2_rn(sigmoidf_(r.x), sigmoidf_(r.y));
        __half2 s23 = __floats2half2_rn(sigmoidf_(r.z), sigmoidf_(r.w));
        __half2* sp = (__half2*)&g_sig[(size_t)eg * 64 + 4 * tx];
        sp[0] = s01;
        sp[1] = s23;
    }
}

// ---------------- fused aggregation + h update: 2 nodes per 128-thread block ----------------
__global__ void k_agg(const int* __restrict__ src, const int* __restrict__ dst) {
    __shared__ float sf[2][64], sb[2][64];
    int tid = threadIdx.x;        // 128 = 4 warps
    int warp = tid >> 5, lane = tid & 31;
    int nb = warp >> 1;           // node in block: 0 or 1
    bool fwd = (warp & 1) == 0;
    int n = blockIdx.x * 2 + nb;
    const int* ofs = fwd ? g_ofs_in : g_ofs_out;
    const int* csr = fwd ? g_csr_in : g_csr_out;
    const int* oth = fwd ? src : dst;
    int off2 = fwd ? 0 : 64;      // A2h fwd, A3h bwd (within g_hwh)
    int beg = ofs[n], end = ofs[n + 1];
    float nx = 0.f, ny = 0.f, dx = 0.f, dy = 0.f;
    const unsigned FULL = 0xffffffffu;
    int jc = 2 * lane;
    for (int c = beg; c < end; c += 32) {
        int m = end - c; if (m > 32) m = 32;
        int e_l = (lane < m) ? __ldg(&csr[c + lane]) : 0;
        int o_l = (lane < m) ? __ldg(&oth[e_l]) : 0;
        int q = 0;
        for (; q + 3 < m; q += 4) {
            int e0 = __shfl_sync(FULL, e_l, q),     e1 = __shfl_sync(FULL, e_l, q + 1);
            int e2 = __shfl_sync(FULL, e_l, q + 2), e3 = __shfl_sync(FULL, e_l, q + 3);
            int o0 = __shfl_sync(FULL, o_l, q),     o1 = __shfl_sync(FULL, o_l, q + 1);
            int o2 = __shfl_sync(FULL, o_l, q + 2), o3 = __shfl_sync(FULL, o_l, q + 3);
            float2 s0 = __half22float2(*(const __half2*)&g_sig[(size_t)e0 * 64 + jc]);
            float2 s1 = __half22float2(*(const __half2*)&g_sig[(size_t)e1 * 64 + jc]);
            float2 s2 = __half22float2(*(const __half2*)&g_sig[(size_t)e2 * 64 + jc]);
            float2 s3 = __half22float2(*(const __half2*)&g_sig[(size_t)e3 * 64 + jc]);
            float2 h0 = __half22float2(*(const __half2*)&g_hwh[(size_t)o0 * 128 + off2 + jc]);
            float2 h1 = __half22float2(*(const __half2*)&g_hwh[(size_t)o1 * 128 + off2 + jc]);
            float2 h2 = __half22float2(*(const __half2*)&g_hwh[(size_t)o2 * 128 + off2 + jc]);
            float2 h3 = __half22float2(*(const __half2*)&g_hwh[(size_t)o3 * 128 + off2 + jc]);
            nx += s0.x * h0.x + s1.x * h1.x + s2.x * h2.x + s3.x * h3.x;
            ny += s0.y * h0.y + s1.y * h1.y + s2.y * h2.y + s3.y * h3.y;
            dx += (s0.x + s1.x) + (s2.x + s3.x);
            dy += (s0.y + s1.y) + (s2.y + s3.y);
        }
        for (; q < m; q++) {
            int e0 = __shfl_sync(FULL, e_l, q);
            int o0 = __shfl_sync(FULL, o_l, q);
            float2 s0 = __half22float2(*(const __half2*)&g_sig[(size_t)e0 * 64 + jc]);
            float2 h0 = __half22float2(*(const __half2*)&g_hwh[(size_t)o0 * 128 + off2 + jc]);
            nx += s0.x * h0.x;
            ny += s0.y * h0.y;
            dx += s0.x;
            dy += s0.y;
        }
    }
    float* dstp = fwd ? sf[nb] : sb[nb];
    dstp[jc] = nx / (dx + EPSV);
    dstp[jc + 1] = ny / (dy + EPSV);
    __syncthreads();
    {
        int nb2 = tid >> 6, j = tid & 63;
        int n2 = blockIdx.x * 2 + nb2;
        float v = g_hw[(size_t)n2 * 320 + j] + sf[nb2][j] + sb[nb2][j];
        g_h[n2 * 64 + j] += fmaxf(v, 0.f);
    }
}

// ---------------- h += x2 @ base_W + base_b ----------------
__global__ void k_base(const float* __restrict__ base_W, const float* __restrict__ base_b) {
    int idx = blockIdx.x * blockDim.x + threadIdx.x;
    if (idx < NN * 64) {
        int n = idx >> 6, j = idx & 63;
        float v = g_x2[n * 4 + 0] * base_W[j] + g_x2[n * 4 + 1] * base_W[64 + j]
                + g_x2[n * 4 + 2] * base_W[128 + j] + g_x2[n * 4 + 3] * base_W[192 + j] + base_b[j];
        g_h[idx] += v;
    }
}

// ---------------- prediction head, stage 1: per-node projections (tiled GEMM, 2 matrices) ----------------
__global__ void __launch_bounds__(256)
k_prednode(const float* __restrict__ Wp1) {
    __shared__ float hsT[64][68];
    __shared__ float ws[64][68];
    int tid = threadIdx.x;
    int tx = tid & 15, ty = tid >> 4;
    int n0 = blockIdx.x * 64;
    int m = blockIdx.y;   // 0: src-part, 1: dst-part
    const float* Wm = Wp1 + (size_t)m * 4096;
#pragma unroll
    for (int i = 0; i < 16; i++) {
        int idx = tid + 256 * i;
        int rr = idx >> 6, cc = idx & 63;
        ws[rr][cc] = Wm[idx];
        int n = n0 + rr;
        hsT[cc][rr] = (n < NN) ? g_h[(size_t)n * 64 + cc] : 0.f;
    }
    __syncthreads();
    float acc[4][4] = {{0.f}};
#pragma unroll 16
    for (int k = 0; k < 64; k++) {
        float4 a = *(const float4*)&hsT[k][4 * ty];
        float4 b = *(const float4*)&ws[k][4 * tx];
        acc[0][0] += a.x * b.x; acc[0][1] += a.x * b.y; acc[0][2] += a.x * b.z; acc[0][3] += a.x * b.w;
        acc[1][0] += a.y * b.x; acc[1][1] += a.y * b.y; acc[1][2] += a.y * b.z; acc[1][3] += a.y * b.w;
        acc[2][0] += a.z * b.x; acc[2][1] += a.z * b.y; acc[2][2] += a.z * b.z; acc[2][3] += a.z * b.w;
        acc[3][0] += a.w * b.x; acc[3][1] += a.w * b.y; acc[3][2] += a.w * b.z; acc[3][3] += a.w * b.w;
    }
#pragma unroll
    for (int i = 0; i < 4; i++) {
        int n = n0 + 4 * ty + i;
        if (n >= NN) break;
        float4 r;
        r.x = acc[i][0]; r.y = acc[i][1]; r.z = acc[i][2]; r.w = acc[i][3];
        *(float4*)&g_hw[(size_t)n * 320 + m * 64 + 4 * tx] = r;
    }
}

// ---------------- prediction head, stage 2: per-edge (tiled GEMM + reduce) ----------------
__global__ void __launch_bounds__(256)
k_prededge(const int* __restrict__ src, const int* __restrict__ dst,
           const float* __restrict__ Wp1, const float* __restrict__ bp1,
           const float* __restrict__ Wp2, const float* __restrict__ bp2,
           float* __restrict__ out) {
    __shared__ float es[64][68];
    __shared__ float ws[64][68];
    __shared__ int ssrc[64], sdst[64];
    __shared__ float part[64][17];   // per-edge partial sums by tx (padded)
    int tid = threadIdx.x;
    int tx = tid & 15, ty = tid >> 4;
    int e0 = blockIdx.x * 64;
    const float* Wc = Wp1 + (size_t)128 * 64;
#pragma unroll
    for (int i = 0; i < 4; i++) {
        int idx = tid + 256 * i;
        int r4 = idx >> 4, c4 = idx & 15;
        float4 ev = *(const float4*)&g_e[(size_t)(e0 + r4) * 64 + 4 * c4];
        *(float4*)&es[r4][4 * c4] = ev;
        float4 wv = *(const float4*)&Wc[(size_t)r4 * 64 + 4 * c4];
        *(float4*)&ws[r4][4 * c4] = wv;
    }
    if (tid < 64) { ssrc[tid] = src[e0 + tid]; sdst[tid] = dst[e0 + tid]; }
    __syncthreads();
    float acc[4][4] = {{0.f}};
#pragma unroll
    for (int k4 = 0; k4 < 16; k4++) {
        int k = 4 * k4;
        float4 a0 = *(const float4*)&es[4 * ty + 0][k];
        float4 a1 = *(const float4*)&es[4 * ty + 1][k];
        float4 a2 = *(const float4*)&es[4 * ty + 2][k];
        float4 a3 = *(const float4*)&es[4 * ty + 3][k];
        float4 b0 = *(const float4*)&ws[k + 0][4 * tx];
        float4 b1 = *(const float4*)&ws[k + 1][4 * tx];
        float4 b2 = *(const float4*)&ws[k + 2][4 * tx];
        float4 b3 = *(const float4*)&ws[k + 3][4 * tx];
        acc[0][0] += a0.x * b0.x + a0.y * b1.x + a0.z * b2.x + a0.w * b3.x;
        acc[0][1] += a0.x * b0.y + a0.y * b1.y + a0.z * b2.y + a0.w * b3.y;
        acc[0][2] += a0.x * b0.z + a0.y * b1.z + a0.z * b2.z + a0.w * b3.z;
        acc[0][3] += a0.x * b0.w + a0.y * b1.w + a0.z * b2.w + a0.w * b3.w;
        acc[1][0] += a1.x * b0.x + a1.y * b1.x + a1.z * b2.x + a1.w * b3.x;
        acc[1][1] += a1.x * b0.y + a1.y * b1.y + a1.z * b2.y + a1.w * b3.y;
        acc[1][2] += a1.x * b0.z + a1.y * b1.z + a1.z * b2.z + a1.w * b3.z;
        acc[1][3] += a1.x * b0.w + a1.y * b1.w + a1.z * b2.w + a1.w * b3.w;
        acc[2][0] += a2.x * b0.x + a2.y * b1.x + a2.z * b2.x + a2.w * b3.x;
        acc[2][1] += a2.x * b0.y + a2.y * b1.y + a2.z * b2.y + a2.w * b3.y;
        acc[2][2] += a2.x * b0.z + a2.y * b1.z + a2.z * b2.z + a2.w * b3.z;
        acc[2][3] += a2.x * b0.w + a2.y * b1.w + a2.z * b2.w + a2.w * b3.w;
        acc[3][0] += a3.x * b0.x + a3.y * b1.x + a3.z * b2.x + a3.w * b3.x;
        acc[3][1] += a3.x * b0.y + a3.y * b1.y + a3.z * b2.y + a3.w * b3.y;
        acc[3][2] += a3.x * b0.z + a3.y * b1.z + a3.z * b2.z + a3.w * b3.z;
        acc[3][3] += a3.x * b0.w + a3.y * b1.w + a3.z * b2.w + a3.w * b3.w;
    }
    float4 bias = *(const float4*)&bp1[4 * tx];
    float4 w2 = *(const float4*)&Wp2[4 * tx];
    float bp2v = bp2[0];
#pragma unroll
    for (int i = 0; i < 4; i++) {
        int el = 4 * ty + i;
        int s = ssrc[el], d = sdst[el];
        float4 h1 = *(const float4*)&g_hw[(size_t)s * 320 + 4 * tx];
        float4 h2 = *(const float4*)&g_hw[(size_t)d * 320 + 64 + 4 * tx];
        float p = fmaxf(acc[i][0] + bias.x + h1.x + h2.x, 0.f) * w2.x
                + fmaxf(acc[i][1] + bias.y + h1.y + h2.y, 0.f) * w2.y
                + fmaxf(acc[i][2] + bias.z + h1.z + h2.z, 0.f) * w2.z
                + fmaxf(acc[i][3] + bias.w + h1.w + h2.w, 0.f) * w2.w;
        part[el][tx] = p;
    }
    __syncthreads();
    if (tid < 64) {
        float s = 0.f;
#pragma unroll
        for (int q = 0; q < 16; q++) s += part[tid][q];
        out[e0 + tid] = s + bp2v;
    }
}

// ---------------- launch ----------------
extern "C" void kernel_launch(void* const* d_in, const int* in_sizes, int n_in,
                              void* d_out, int out_size) {
    const float* x        = (const float*)d_in[0];
    const float* e_in     = (const float*)d_in[1];
    const float* reads    = (const float*)d_in[2];
    const int*   src      = (const int*)d_in[3];
    const int*   dst      = (const int*)d_in[4];
    const int*   rl       = (const int*)d_in[5];
    const float* W1n      = (const float*)d_in[6];
    const float* b1n      = (const float*)d_in[7];
    const float* W2n      = (const float*)d_in[8];
    const float* b2n      = (const float*)d_in[9];
    const float* W1e      = (const float*)d_in[10];
    const float* b1e      = (const float*)d_in[11];
    const float* W2e      = (const float*)d_in[12];
    const float* b2e      = (const float*)d_in[13];
    const float* gnn_W    = (const float*)d_in[14];
    const float* gnn_b    = (const float*)d_in[15];
    const float* in_projW = (const float*)d_in[16];
    const float* conv_W   = (const float*)d_in[17];
    const float* conv_b   = (const float*)d_in[18];
    const float* x_projW  = (const float*)d_in[19];
    const float* dt_projW = (const float*)d_in[20];
    const float* dt_projb = (const float*)d_in[21];
    const float* A_log    = (const float*)d_in[22];
    const float* Dskip    = (const float*)d_in[23];
    const float* out_projW= (const float*)d_in[24];
    const float* base_W   = (const float*)d_in[25];
    const float* base_b   = (const float*)d_in[26];
    const float* Wp1      = (const float*)d_in[27];
    const float* bp1      = (const float*)d_in[28];
    const float* Wp2      = (const float*)d_in[29];
    const float* bp2      = (const float*)d_in[30];
    float* out = (float*)d_out;

    static cudaStream_t s1 = nullptr, s2 = nullptr;
    static cudaEvent_t evFork = nullptr, evEnc = nullptr, evMamba = nullptr;
    static cudaEvent_t evA[NLAYERS], evAgg[NLAYERS];
    if (s1 == nullptr) {
        int prLow = 0, prHigh = 0;
        cudaDeviceGetStreamPriorityRange(&prLow, &prHigh);   // prLow = least priority
        cudaStreamCreateWithPriority(&s1, cudaStreamNonBlocking, prHigh);  // GNN helper: high
        cudaStreamCreateWithPriority(&s2, cudaStreamNonBlocking, prLow);   // mamba: low
        cudaEventCreateWithFlags(&evFork, cudaEventDisableTiming);
        cudaEventCreateWithFlags(&evEnc, cudaEventDisableTiming);
        cudaEventCreateWithFlags(&evMamba, cudaEventDisableTiming);
        for (int l = 0; l < NLAYERS; l++) {
            cudaEventCreateWithFlags(&evA[l], cudaEventDisableTiming);
            cudaEventCreateWithFlags(&evAgg[l], cudaEventDisableTiming);
        }
    }

    dim3 hwGridA((NN + 63) / 64, 3);   // m = 0,1,2 (A1,A2,A3)
    dim3 hwGridB((NN + 63) / 64, 2);   // m = 3,4 (B1,B2)
    dim3 pnGrid((NN + 63) / 64, 2);

    // main: node encoder (idx 0), fork
    k_enc<<<512, 256>>>(x, W1n, b1n, W2n, b2n, NN, 0);               // 0
    cudaEventRecord(evFork, 0);

    // s2 (low prio): edge encoder overlaps with main's hwB
    cudaStreamWaitEvent(s2, evFork, 0);
    k_enc<<<2048, 256, 0, s2>>>(e_in, W1e, b1e, W2e, b2e, EE, 1);    // 1
    cudaEventRecord(evEnc, s2);

    // main: hwB then edge l0 (idx 3 -> ncu sample)
    k_hw<<<hwGridB, 256>>>(gnn_W, gnn_b, 0, 3);                      // 2
    cudaStreamWaitEvent(0, evEnc, 0);
    k_edge<<<EE / 128, 256>>>(src, dst, gnn_W, gnn_b, 0);            // 3 <- profiled

    // s1 (high prio): CSR build + A-part hw for layer 0
    cudaStreamWaitEvent(s1, evFork, 0);
    k_zero_deg<<<(NN + 255) / 256, 256, 0, s1>>>();
    k_hist<<<(EE + 255) / 256, 256, 0, s1>>>(src, dst);
    k_scan<<<1, 1024, 0, s1>>>();
    k_fill<<<(EE + 255) / 256, 256, 0, s1>>>(src, dst);
    k_sortcsr<<<(2 * NN * 32 + 255) / 256, 256, 0, s1>>>();
    k_hw<<<hwGridA, 256, 0, s1>>>(gnn_W, gnn_b, 0, 0);
    cudaEventRecord(evA[0], s1);

    // s2 (low prio): mamba backfills idle SMs behind the GNN chain
    k_rlscanplace<<<1, 256, 0, s2>>>(rl);
    k_mamba<<<1250, 256, 0, s2>>>(reads, rl, in_projW, conv_W, conv_b,
                                  x_projW, dt_projW, dt_projb, A_log, Dskip, out_projW);
    cudaEventRecord(evMamba, s2);

    // main: layer 0 aggregation (needs CSR + A-part, both via evA[0])
    cudaStreamWaitEvent(0, evA[0], 0);
    k_agg<<<NN / 2, 128>>>(src, dst);
    cudaEventRecord(evAgg[0], 0);

    // layers 1..7: interleaved issue order (every wait follows its record)
    for (int l = 1; l < NLAYERS; l++) {
        cudaStreamWaitEvent(s1, evAgg[l - 1], 0);
        k_hw<<<hwGridA, 256, 0, s1>>>(gnn_W, gnn_b, l, 0);
        cudaEventRecord(evA[l], s1);
        k_hw<<<hwGridB, 256>>>(gnn_W, gnn_b, l, 3);
        k_edge<<<EE / 128, 256>>>(src, dst, gnn_W, gnn_b, l);
        cudaStreamWaitEvent(0, evA[l], 0);
        k_agg<<<NN / 2, 128>>>(src, dst);
        cudaEventRecord(evAgg[l], 0);
    }

    // base add needs mamba result
    cudaStreamWaitEvent(0, evMamba, 0);
    k_base<<<(NN * 64 + 255) / 256, 256>>>(base_W, base_b);
    k_prednode<<<pnGrid, 256>>>(Wp1);
    k_prededge<<<EE / 64, 256>>>(src, dst, Wp1, bp1, Wp2, bp2, out);
}

// round 17
// speedup vs baseline: 1.0106x; 1.0106x over previous
#include <cuda_runtime.h>
#include <cuda_fp16.h>

// ---------------- problem constants ----------------
#define NN 10000
#define LL 256
#define EE 160000
#define HH 64
#define DM 4
#define DS 32
#define DC 4
#define DI 8
#define NLAYERS 8
#define EPSV 1e-6f

// ---------------- scratch (device globals; no allocation) ----------------
__device__ float g_h[NN * HH];          // node features
__device__ float g_e[EE * HH];          // edge features (updated in place)
__device__ __half g_sig[EE * HH];       // sigmoid(e) cache (written by k_edge)
__device__ float g_hw[NN * 5 * HH];     // A1|A2|A3|B1|B2 per node (reused by pred)
__device__ __half g_hwh[NN * 128];      // fp16 copy of A2h|A3h for aggregation gathers
__device__ float g_x2[NN * DM];
__device__ int g_deg_in[NN], g_deg_out[NN];
__device__ int g_ofs_in[NN + 1], g_ofs_out[NN + 1];
__device__ int g_cur_in[NN], g_cur_out[NN];
__device__ int g_csr_in[EE], g_csr_out[EE];
__device__ int g_order[NN];

__device__ __forceinline__ float sigmoidf_(float x) {
    return 1.f / (1.f + __expf(-x));
}

// ---------------- CSR build ----------------
__global__ void k_zero_deg() {
    int i = blockIdx.x * blockDim.x + threadIdx.x;
    if (i < NN) { g_deg_in[i] = 0; g_deg_out[i] = 0; }
}

__global__ void k_hist(const int* __restrict__ src, const int* __restrict__ dst) {
    int i = blockIdx.x * blockDim.x + threadIdx.x;
    if (i < EE) {
        atomicAdd(&g_deg_in[dst[i]], 1);
        atomicAdd(&g_deg_out[src[i]], 1);
    }
}

__global__ void k_scan() {
    __shared__ int part[1024];
    int t = threadIdx.x;
    for (int pass = 0; pass < 2; pass++) {
        const int* deg = pass ? g_deg_out : g_deg_in;
        int* ofs = pass ? g_ofs_out : g_ofs_in;
        int* cur = pass ? g_cur_out : g_cur_in;
        int lo = t * 10;
        int hi = lo + 10; if (hi > NN) hi = NN;
        int s = 0;
        for (int i = lo; i < hi && i < NN; i++) s += deg[i];
        part[t] = s;
        __syncthreads();
        for (int d = 1; d < 1024; d <<= 1) {
            int add = (t >= d) ? part[t - d] : 0;
            __syncthreads();
            part[t] += add;
            __syncthreads();
        }
        int run = part[t] - s;  // exclusive base
        for (int i = lo; i < hi && i < NN; i++) {
            ofs[i] = run; cur[i] = run; run += deg[i];
        }
        if (lo < NN && hi == NN) ofs[NN] = run;
        __syncthreads();
    }
}

__global__ void k_fill(const int* __restrict__ src, const int* __restrict__ dst) {
    int i = blockIdx.x * blockDim.x + threadIdx.x;
    if (i < EE) {
        int p = atomicAdd(&g_cur_in[dst[i]], 1);
        g_csr_in[p] = i;
        int q = atomicAdd(&g_cur_out[src[i]], 1);
        g_csr_out[q] = i;
    }
}

// deterministic order: warp-bitonic sort of each node's edge-id segment (len<=64 fast path)
__global__ void k_sortcsr() {
    int gw = (blockIdx.x * blockDim.x + threadIdx.x) >> 5;
    int lane = threadIdx.x & 31;
    if (gw >= 2 * NN) return;
    int n = (gw < NN) ? gw : gw - NN;
    int* csr = (gw < NN) ? g_csr_in : g_csr_out;
    const int* ofs = (gw < NN) ? g_ofs_in : g_ofs_out;
    int beg = ofs[n], end = ofs[n + 1];
    int len = end - beg;
    if (len <= 1) return;
    if (len <= 64) {
        const int INF = 0x7fffffff;
        int a = (lane < len) ? csr[beg + lane] : INF;
        int b = (32 + lane < len) ? csr[beg + 32 + lane] : INF;
#pragma unroll
        for (int k = 2; k <= 64; k <<= 1) {
#pragma unroll
            for (int j = 32; j > 0; j >>= 1) {
                if (j >= k) continue;
                if (j == 32) {
                    int lo = min(a, b), hi = max(a, b);
                    a = lo; b = hi;
                } else {
                    int pa = __shfl_xor_sync(0xffffffffu, a, j);
                    bool upa = ((lane & j) == 0);
                    bool asca = ((lane & k) == 0);
                    a = (upa == asca) ? min(a, pa) : max(a, pa);
                    int pb = __shfl_xor_sync(0xffffffffu, b, j);
                    int idxb = lane + 32;
                    bool upb = ((idxb & j) == 0);
                    bool ascb = ((idxb & k) == 0);
                    b = (upb == ascb) ? min(b, pb) : max(b, pb);
                }
            }
        }
        if (lane < len) csr[beg + lane] = a;
        if (32 + lane < len) csr[beg + 32 + lane] = b;
    } else {
        if (lane == 0) {
            for (int i = beg + 1; i < end; i++) {
                int key = csr[i]; int j = i - 1;
                while (j >= beg && csr[j] > key) { csr[j + 1] = csr[j]; j--; }
                csr[j + 1] = key;
            }
        }
    }
}

// ---------------- read_length binning: fused hist+scan+place, descending rl (LPT) ----------------
__global__ void k_rlscanplace(const int* __restrict__ rl) {
    __shared__ int sbin[LL];
    __shared__ int sofs[LL];
    int t = threadIdx.x;  // 256
    sbin[t] = 0;
    __syncthreads();
    for (int i = t; i < NN; i += 256) atomicAdd(&sbin[rl[i] - 1], 1);
    __syncthreads();
    int v = sbin[t];
    for (int d = 1; d < LL; d <<= 1) {
        int add = (t >= d) ? sbin[t - d] : 0;
        __syncthreads();
        sbin[t] += add;
        __syncthreads();
    }
    sofs[t] = sbin[t] - v;  // exclusive (ascending)
    __syncthreads();
    for (int i = t; i < NN; i += 256) {
        int pos = atomicAdd(&sofs[rl[i] - 1], 1);
        g_order[NN - 1 - pos] = i;   // descending rl -> LPT scheduling
    }
}

// ---------------- mamba: warp per node (rl-sorted desc), lane = state index ----------------
__global__ void k_mamba(const float* __restrict__ reads, const int* __restrict__ read_length,
                        const float* __restrict__ in_proj_W, const float* __restrict__ conv_W,
                        const float* __restrict__ conv_b, const float* __restrict__ x_proj_W,
                        const float* __restrict__ dt_proj_W, const float* __restrict__ dt_proj_b,
                        const float* __restrict__ A_log, const float* __restrict__ Dskip,
                        const float* __restrict__ out_proj_W) {
    __shared__ float op[32];
    __shared__ float ys[8][8], os[8][8];
    int tid = threadIdx.x;
    if (tid < 32) op[tid] = out_proj_W[tid];
    __syncthreads();
    int warp = tid >> 5, lane = tid & 31;
    int idx = blockIdx.x * 8 + warp;
    if (idx >= NN) return;
    int li = lane & 7;

    float ipx[4], ipz[4], cwr[4];
#pragma unroll
    for (int m = 0; m < 4; m++) {
        ipx[m] = __ldg(&in_proj_W[m * 16 + li]);
        ipz[m] = __ldg(&in_proj_W[m * 16 + 8 + li]);
        cwr[m] = __ldg(&conv_W[li * 4 + m]);
    }
    float cbr = __ldg(&conv_b[li]);
    float dtwr = __ldg(&dt_proj_W[li]);
    float dtbr = __ldg(&dt_proj_b[li]);
    float dskr = __ldg(&Dskip[li]);
    float xp0r[8], xpBr[8], xpCr[8], Asr[8];
#pragma unroll
    for (int i = 0; i < 8; i++) {
        xp0r[i] = __ldg(&x_proj_W[i * 65]);
        xpBr[i] = __ldg(&x_proj_W[i * 65 + 1 + lane]);
        xpCr[i] = __ldg(&x_proj_W[i * 65 + 33 + lane]);
        Asr[i] = -__expf(__ldg(&A_log[i * 32 + lane]));
    }

    int n = g_order[idx];
    int rl = read_length[n];
    float hst[8];
#pragma unroll
    for (int i = 0; i < 8; i++) hst[i] = 0.f;
    float c0 = 0.f, c1 = 0.f, c2 = 0.f;
    float xc = 0.f, zf = 0.f, CsLast = 0.f;
    const float4* rd4 = (const float4*)(reads + (size_t)n * LL * 4);
    float4 rd = rd4[0];

    for (int t = 0; t < rl; t++) {
        int tn = (t + 1 < rl) ? (t + 1) : t;
        float4 nxt = rd4[tn];                          // prefetch
        float xh = rd.x * ipx[0] + rd.y * ipx[1] + rd.z * ipx[2] + rd.w * ipx[3];
        float c = c0 * cwr[0] + c1 * cwr[1] + c2 * cwr[2] + xh * cwr[3] + cbr;
        c0 = c1; c1 = c2; c2 = xh;
        xc = c * sigmoidf_(c);
        if (t == rl - 1)
            zf = rd.x * ipz[0] + rd.y * ipz[1] + rd.z * ipz[2] + rd.w * ipz[3];

        float xr[8];
        float dbl0 = 0.f, Bs = 0.f, Cs = 0.f;
#pragma unroll
        for (int i = 0; i < 8; i++) {
            float xi = __shfl_sync(0xffffffffu, xc, i);
            xr[i] = xi;
            dbl0 += xi * xp0r[i];
            Bs += xi * xpBr[i];
            Cs += xi * xpCr[i];
        }
        float dr = dbl0 * dtwr + dtbr;
        float dtv = (dr > 15.f) ? dr : __logf(1.f + __expf(dr));
#pragma unroll
        for (int i = 0; i < 8; i++) {
            float dti = __shfl_sync(0xffffffffu, dtv, i);
            hst[i] = __expf(dti * Asr[i]) * hst[i] + (dti * Bs) * xr[i];
        }
        if (t == rl - 1) CsLast = Cs;
        rd = nxt;
    }
#pragma unroll
    for (int i = 0; i < 8; i++) {
        float v = hst[i] * CsLast;
#pragma unroll
        for (int off = 16; off; off >>= 1) v += __shfl_xor_sync(0xffffffffu, v, off);
        if (lane == 0) ys[warp][i] = v;
    }
    __syncwarp();
    if (lane < 8) {
        float y = ys[warp][lane] + xc * dskr;
        os[warp][lane] = y * (zf * sigmoidf_(zf));
    }
    __syncwarp();
    if (lane < 4) {
        float acc = 0.f;
#pragma unroll
        for (int i = 0; i < 8; i++) acc += os[warp][i] * op[i * 4 + lane];
        g_x2[n * 4 + lane] = acc;
    }
}

// ---------------- encoders ----------------
__global__ void k_enc(const float* __restrict__ in, const float* __restrict__ W1,
                      const float* __restrict__ b1, const float* __restrict__ W2,
                      const float* __restrict__ b2, int rows, int target_e) {
    float* outp = target_e ? g_e : g_h;
    int tid = threadIdx.x;
    int j = tid & 63, g = tid >> 6;
    float w1a[16], w1b[16], bb1[16], w2c[16];
#pragma unroll
    for (int i = 0; i < 16; i++) {
        w1a[i] = W1[i];
        w1b[i] = W1[16 + i];
        bb1[i] = b1[i];
        w2c[i] = W2[i * 64 + j];
    }
    float b2j = b2[j];
    for (int r = blockIdx.x * 4 + g; r < rows; r += gridDim.x * 4) {
        float x0 = in[r * 2], x1 = in[r * 2 + 1];
        float acc = b2j;
#pragma unroll
        for (int i = 0; i < 16; i++) {
            float hid = fmaxf(x0 * w1a[i] + x1 * w1b[i] + bb1[i], 0.f);
            acc += hid * w2c[i];
        }
        outp[r * 64 + j] = acc;
    }
}

// ---------------- node GEMM (tiled): g_hw[:, m*64:(m+1)*64] = h @ W_m + b_m, m = blockIdx.y ----------------
// also writes fp16 copies of A2h (m=1) and A3h (m=2) into g_hwh for the aggregation gathers
__global__ void __launch_bounds__(256)
k_hw(const float* __restrict__ gnn_W, const float* __restrict__ gnn_b, int l) {
    __shared__ float hsT[64][68];   // hsT[k][node_local]
    __shared__ float ws[64][68];    // ws[k][c]
    int tid = threadIdx.x;
    int tx = tid & 15, ty = tid >> 4;
    int n0 = blockIdx.x * 64;
    int m = blockIdx.y;
    const float* Wm = gnn_W + (size_t)(l * 6 + m) * 4096;
#pragma unroll
    for (int i = 0; i < 16; i++) {
        int idx = tid + 256 * i;
        int rr = idx >> 6, cc = idx & 63;
        ws[rr][cc] = Wm[idx];
        int n = n0 + rr;
        hsT[cc][rr] = (n < NN) ? g_h[(size_t)n * 64 + cc] : 0.f;
    }
    __syncthreads();
    float acc[4][4] = {{0.f}};
#pragma unroll 16
    for (int k = 0; k < 64; k++) {
        float4 a = *(const float4*)&hsT[k][4 * ty];
        float4 b = *(const float4*)&ws[k][4 * tx];
        acc[0][0] += a.x * b.x; acc[0][1] += a.x * b.y; acc[0][2] += a.x * b.z; acc[0][3] += a.x * b.w;
        acc[1][0] += a.y * b.x; acc[1][1] += a.y * b.y; acc[1][2] += a.y * b.z; acc[1][3] += a.y * b.w;
        acc[2][0] += a.z * b.x; acc[2][1] += a.z * b.y; acc[2][2] += a.z * b.z; acc[2][3] += a.z * b.w;
        acc[3][0] += a.w * b.x; acc[3][1] += a.w * b.y; acc[3][2] += a.w * b.z; acc[3][3] += a.w * b.w;
    }
    const float* bm = gnn_b + (size_t)(l * 6 + m) * 64;
    float4 bias = *(const float4*)&bm[4 * tx];
#pragma unroll
    for (int i = 0; i < 4; i++) {
        int n = n0 + 4 * ty + i;
        if (n >= NN) break;
        float4 r;
        r.x = acc[i][0] + bias.x;
        r.y = acc[i][1] + bias.y;
        r.z = acc[i][2] + bias.z;
        r.w = acc[i][3] + bias.w;
        *(float4*)&g_hw[(size_t)n * 320 + m * 64 + 4 * tx] = r;
        if (m == 1 || m == 2) {   // A2h / A3h fp16 copy for k_agg
            __half2 p01 = __floats2half2_rn(r.x, r.y);
            __half2 p23 = __floats2half2_rn(r.z, r.w);
            __half2* hp = (__half2*)&g_hwh[(size_t)n * 128 + (m - 1) * 64 + 4 * tx];
            hp[0] = p01;
            hp[1] = p23;
        }
    }
}

// ---------------- per-layer edge update: 128-edge tile, thread = 8 edges x 4 channels ----------------
// grid 1250, block 256; EE = 1250*128 exactly
__global__ void __launch_bounds__(256)
k_edge(const int* __restrict__ src, const int* __restrict__ dst,
       const float* __restrict__ gnn_W, const float* __restrict__ gnn_b, int l) {
    __shared__ float es[128][64];   // es[edge][k], row-major
    __shared__ float ws[64][64];    // ws[k][c]
    __shared__ int ssrc[128], sdst[128];
    int tid = threadIdx.x;
    int tx = tid & 15, ty = tid >> 4;   // tx: channel group (4*tx), ty: edge group (8*ty)
    int e0 = blockIdx.x * 128;
    const float* W5 = gnn_W + (size_t)(l * 6 + 5) * 4096;
#pragma unroll
    for (int i = 0; i < 8; i++) {
        int idx = tid + 256 * i;            // float4 idx 0..2047
        int r4 = idx >> 4, c4 = idx & 15;
        float4 ev = *(const float4*)&g_e[(size_t)(e0 + r4) * 64 + 4 * c4];
        *(float4*)&es[r4][4 * c4] = ev;
    }
#pragma unroll
    for (int i = 0; i < 4; i++) {
        int idx = tid + 256 * i;            // float4 idx 0..1023
        int r4 = idx >> 4, c4 = idx & 15;
        float4 wv = *(const float4*)&W5[(size_t)r4 * 64 + 4 * c4];
        *(float4*)&ws[r4][4 * c4] = wv;
    }
    if (tid < 128) { ssrc[tid] = src[e0 + tid]; sdst[tid] = dst[e0 + tid]; }
    __syncthreads();
    float acc[8][4] = {{0.f}};
#pragma unroll
    for (int k4 = 0; k4 < 16; k4++) {
        int k = 4 * k4;
        float4 b0 = *(const float4*)&ws[k + 0][4 * tx];
        float4 b1 = *(const float4*)&ws[k + 1][4 * tx];
        float4 b2 = *(const float4*)&ws[k + 2][4 * tx];
        float4 b3 = *(const float4*)&ws[k + 3][4 * tx];
#pragma unroll
        for (int i = 0; i < 8; i++) {
            float4 a = *(const float4*)&es[8 * ty + i][k];
            acc[i][0] += a.x * b0.x + a.y * b1.x + a.z * b2.x + a.w * b3.x;
            acc[i][1] += a.x * b0.y + a.y * b1.y + a.z * b2.y + a.w * b3.y;
            acc[i][2] += a.x * b0.z + a.y * b1.z + a.z * b2.z + a.w * b3.z;
            acc[i][3] += a.x * b0.w + a.y * b1.w + a.z * b2.w + a.w * b3.w;
        }
    }
    const float* b5 = gnn_b + (size_t)(l * 6 + 5) * 64;
    float4 bias = *(const float4*)&b5[4 * tx];
#pragma unroll
    for (int i = 0; i < 8; i++) {
        int el = 8 * ty + i;
        int eg = e0 + el;
        int s = ssrc[el], d = sdst[el];
        float4 h1 = *(const float4*)&g_hw[(size_t)s * 320 + 192 + 4 * tx];
        float4 h2 = *(const float4*)&g_hw[(size_t)d * 320 + 256 + 4 * tx];
        float4 ea = *(const float4*)&es[el][4 * tx];
        float4 r;
        r.x = ea.x + fmaxf(acc[i][0] + bias.x + h1.x + h2.x, 0.f);
        r.y = ea.y + fmaxf(acc[i][1] + bias.y + h1.y + h2.y, 0.f);
        r.z = ea.z + fmaxf(acc[i][2] + bias.z + h1.z + h2.z, 0.f);
        r.w = ea.w + fmaxf(acc[i][3] + bias.w + h1.w + h2.w, 0.f);
        *(float4*)&g_e[(size_t)eg * 64 + 4 * tx] = r;
        __half2 s01 = __floats2half2_rn(sigmoidf_(r.x), sigmoidf_(r.y));
        __half2 s23 = __floats2half2_rn(sigmoidf_(r.z), sigmoidf_(r.w));
        __half2* sp = (__half2*)&g_sig[(size_t)eg * 64 + 4 * tx];
        sp[0] = s01;
        sp[1] = s23;
    }
}

// ---------------- fused aggregation + h update: 2 nodes per 128-thread block ----------------
__global__ void k_agg(const int* __restrict__ src, const int* __restrict__ dst) {
    __shared__ float sf[2][64], sb[2][64];
    int tid = threadIdx.x;        // 128 = 4 warps
    int warp = tid >> 5, lane = tid & 31;
    int nb = warp >> 1;           // node in block: 0 or 1
    bool fwd = (warp & 1) == 0;
    int n = blockIdx.x * 2 + nb;
    const int* ofs = fwd ? g_ofs_in : g_ofs_out;
    const int* csr = fwd ? g_csr_in : g_csr_out;
    const int* oth = fwd ? src : dst;
    int off2 = fwd ? 0 : 64;      // A2h fwd, A3h bwd (within g_hwh)
    int beg = ofs[n], end = ofs[n + 1];
    float nx = 0.f, ny = 0.f, dx = 0.f, dy = 0.f;
    const unsigned FULL = 0xffffffffu;
    int jc = 2 * lane;
    for (int c = beg; c < end; c += 32) {
        int m = end - c; if (m > 32) m = 32;
        int e_l = (lane < m) ? __ldg(&csr[c + lane]) : 0;
        int o_l = (lane < m) ? __ldg(&oth[e_l]) : 0;
        int q = 0;
        for (; q + 3 < m; q += 4) {
            int e0 = __shfl_sync(FULL, e_l, q),     e1 = __shfl_sync(FULL, e_l, q + 1);
            int e2 = __shfl_sync(FULL, e_l, q + 2), e3 = __shfl_sync(FULL, e_l, q + 3);
            int o0 = __shfl_sync(FULL, o_l, q),     o1 = __shfl_sync(FULL, o_l, q + 1);
            int o2 = __shfl_sync(FULL, o_l, q + 2), o3 = __shfl_sync(FULL, o_l, q + 3);
            float2 s0 = __half22float2(*(const __half2*)&g_sig[(size_t)e0 * 64 + jc]);
            float2 s1 = __half22float2(*(const __half2*)&g_sig[(size_t)e1 * 64 + jc]);
            float2 s2 = __half22float2(*(const __half2*)&g_sig[(size_t)e2 * 64 + jc]);
            float2 s3 = __half22float2(*(const __half2*)&g_sig[(size_t)e3 * 64 + jc]);
            float2 h0 = __half22float2(*(const __half2*)&g_hwh[(size_t)o0 * 128 + off2 + jc]);
            float2 h1 = __half22float2(*(const __half2*)&g_hwh[(size_t)o1 * 128 + off2 + jc]);
            float2 h2 = __half22float2(*(const __half2*)&g_hwh[(size_t)o2 * 128 + off2 + jc]);
            float2 h3 = __half22float2(*(const __half2*)&g_hwh[(size_t)o3 * 128 + off2 + jc]);
            nx += s0.x * h0.x + s1.x * h1.x + s2.x * h2.x + s3.x * h3.x;
            ny += s0.y * h0.y + s1.y * h1.y + s2.y * h2.y + s3.y * h3.y;
            dx += (s0.x + s1.x) + (s2.x + s3.x);
            dy += (s0.y + s1.y) + (s2.y + s3.y);
        }
        for (; q < m; q++) {
            int e0 = __shfl_sync(FULL, e_l, q);
            int o0 = __shfl_sync(FULL, o_l, q);
            float2 s0 = __half22float2(*(const __half2*)&g_sig[(size_t)e0 * 64 + jc]);
            float2 h0 = __half22float2(*(const __half2*)&g_hwh[(size_t)o0 * 128 + off2 + jc]);
            nx += s0.x * h0.x;
            ny += s0.y * h0.y;
            dx += s0.x;
            dy += s0.y;
        }
    }
    float* dstp = fwd ? sf[nb] : sb[nb];
    dstp[jc] = nx / (dx + EPSV);
    dstp[jc + 1] = ny / (dy + EPSV);
    __syncthreads();
    {
        int nb2 = tid >> 6, j = tid & 63;
        int n2 = blockIdx.x * 2 + nb2;
        float v = g_hw[(size_t)n2 * 320 + j] + sf[nb2][j] + sb[nb2][j];
        g_h[n2 * 64 + j] += fmaxf(v, 0.f);
    }
}

// ---------------- h += x2 @ base_W + base_b ----------------
__global__ void k_base(const float* __restrict__ base_W, const float* __restrict__ base_b) {
    int idx = blockIdx.x * blockDim.x + threadIdx.x;
    if (idx < NN * 64) {
        int n = idx >> 6, j = idx & 63;
        float v = g_x2[n * 4 + 0] * base_W[j] + g_x2[n * 4 + 1] * base_W[64 + j]
                + g_x2[n * 4 + 2] * base_W[128 + j] + g_x2[n * 4 + 3] * base_W[192 + j] + base_b[j];
        g_h[idx] += v;
    }
}

// ---------------- prediction head, stage 1: per-node projections (tiled GEMM, 2 matrices) ----------------
__global__ void __launch_bounds__(256)
k_prednode(const float* __restrict__ Wp1) {
    __shared__ float hsT[64][68];
    __shared__ float ws[64][68];
    int tid = threadIdx.x;
    int tx = tid & 15, ty = tid >> 4;
    int n0 = blockIdx.x * 64;
    int m = blockIdx.y;   // 0: src-part, 1: dst-part
    const float* Wm = Wp1 + (size_t)m * 4096;
#pragma unroll
    for (int i = 0; i < 16; i++) {
        int idx = tid + 256 * i;
        int rr = idx >> 6, cc = idx & 63;
        ws[rr][cc] = Wm[idx];
        int n = n0 + rr;
        hsT[cc][rr] = (n < NN) ? g_h[(size_t)n * 64 + cc] : 0.f;
    }
    __syncthreads();
    float acc[4][4] = {{0.f}};
#pragma unroll 16
    for (int k = 0; k < 64; k++) {
        float4 a = *(const float4*)&hsT[k][4 * ty];
        float4 b = *(const float4*)&ws[k][4 * tx];
        acc[0][0] += a.x * b.x; acc[0][1] += a.x * b.y; acc[0][2] += a.x * b.z; acc[0][3] += a.x * b.w;
        acc[1][0] += a.y * b.x; acc[1][1] += a.y * b.y; acc[1][2] += a.y * b.z; acc[1][3] += a.y * b.w;
        acc[2][0] += a.z * b.x; acc[2][1] += a.z * b.y; acc[2][2] += a.z * b.z; acc[2][3] += a.z * b.w;
        acc[3][0] += a.w * b.x; acc[3][1] += a.w * b.y; acc[3][2] += a.w * b.z; acc[3][3] += a.w * b.w;
    }
#pragma unroll
    for (int i = 0; i < 4; i++) {
        int n = n0 + 4 * ty + i;
        if (n >= NN) break;
        float4 r;
        r.x = acc[i][0]; r.y = acc[i][1]; r.z = acc[i][2]; r.w = acc[i][3];
        *(float4*)&g_hw[(size_t)n * 320 + m * 64 + 4 * tx] = r;
    }
}

// ---------------- prediction head, stage 2: per-edge (128-edge tile GEMM + reduce) ----------------
__global__ void __launch_bounds__(256)
k_prededge(const int* __restrict__ src, const int* __restrict__ dst,
           const float* __restrict__ Wp1, const float* __restrict__ bp1,
           const float* __restrict__ Wp2, const float* __restrict__ bp2,
           float* __restrict__ out) {
    __shared__ float es[128][64];
    __shared__ float ws[64][64];
    __shared__ int ssrc[128], sdst[128];
    __shared__ float part[128][17];
    int tid = threadIdx.x;
    int tx = tid & 15, ty = tid >> 4;
    int e0 = blockIdx.x * 128;
    const float* Wc = Wp1 + (size_t)128 * 64;
#pragma unroll
    for (int i = 0; i < 8; i++) {
        int idx = tid + 256 * i;
        int r4 = idx >> 4, c4 = idx & 15;
        float4 ev = *(const float4*)&g_e[(size_t)(e0 + r4) * 64 + 4 * c4];
        *(float4*)&es[r4][4 * c4] = ev;
    }
#pragma unroll
    for (int i = 0; i < 4; i++) {
        int idx = tid + 256 * i;
        int r4 = idx >> 4, c4 = idx & 15;
        float4 wv = *(const float4*)&Wc[(size_t)r4 * 64 + 4 * c4];
        *(float4*)&ws[r4][4 * c4] = wv;
    }
    if (tid < 128) { ssrc[tid] = src[e0 + tid]; sdst[tid] = dst[e0 + tid]; }
    __syncthreads();
    float acc[8][4] = {{0.f}};
#pragma unroll
    for (int k4 = 0; k4 < 16; k4++) {
        int k = 4 * k4;
        float4 b0 = *(const float4*)&ws[k + 0][4 * tx];
        float4 b1 = *(const float4*)&ws[k + 1][4 * tx];
        float4 b2 = *(const float4*)&ws[k + 2][4 * tx];
        float4 b3 = *(const float4*)&ws[k + 3][4 * tx];
#pragma unroll
        for (int i = 0; i < 8; i++) {
            float4 a = *(const float4*)&es[8 * ty + i][k];
            acc[i][0] += a.x * b0.x + a.y * b1.x + a.z * b2.x + a.w * b3.x;
            acc[i][1] += a.x * b0.y + a.y * b1.y + a.z * b2.y + a.w * b3.y;
            acc[i][2] += a.x * b0.z + a.y * b1.z + a.z * b2.z + a.w * b3.z;
            acc[i][3] += a.x * b0.w + a.y * b1.w + a.z * b2.w + a.w * b3.w;
        }
    }
    float4 bias = *(const float4*)&bp1[4 * tx];
    float4 w2 = *(const float4*)&Wp2[4 * tx];
    float bp2v = bp2[0];
#pragma unroll
    for (int i = 0; i < 8; i++) {
        int el = 8 * ty + i;
        int s = ssrc[el], d = sdst[el];
        float4 h1 = *(const float4*)&g_hw[(size_t)s * 320 + 4 * tx];
        float4 h2 = *(const float4*)&g_hw[(size_t)d * 320 + 64 + 4 * tx];
        float p = fmaxf(acc[i][0] + bias.x + h1.x + h2.x, 0.f) * w2.x
                + fmaxf(acc[i][1] + bias.y + h1.y + h2.y, 0.f) * w2.y
                + fmaxf(acc[i][2] + bias.z + h1.z + h2.z, 0.f) * w2.z
                + fmaxf(acc[i][3] + bias.w + h1.w + h2.w, 0.f) * w2.w;
        part[el][tx] = p;
    }
    __syncthreads();
    if (tid < 128) {
        float s = 0.f;
#pragma unroll
        for (int q = 0; q < 16; q++) s += part[tid][q];
        out[e0 + tid] = s + bp2v;
    }
}

// ---------------- launch: single-stream GNN loop, minimal events ----------------
extern "C" void kernel_launch(void* const* d_in, const int* in_sizes, int n_in,
                              void* d_out, int out_size) {
    const float* x        = (const float*)d_in[0];
    const float* e_in     = (const float*)d_in[1];
    const float* reads    = (const float*)d_in[2];
    const int*   src      = (const int*)d_in[3];
    const int*   dst      = (const int*)d_in[4];
    const int*   rl       = (const int*)d_in[5];
    const float* W1n      = (const float*)d_in[6];
    const float* b1n      = (const float*)d_in[7];
    const float* W2n      = (const float*)d_in[8];
    const float* b2n      = (const float*)d_in[9];
    const float* W1e      = (const float*)d_in[10];
    const float* b1e      = (const float*)d_in[11];
    const float* W2e      = (const float*)d_in[12];
    const float* b2e      = (const float*)d_in[13];
    const float* gnn_W    = (const float*)d_in[14];
    const float* gnn_b    = (const float*)d_in[15];
    const float* in_projW = (const float*)d_in[16];
    const float* conv_W   = (const float*)d_in[17];
    const float* conv_b   = (const float*)d_in[18];
    const float* x_projW  = (const float*)d_in[19];
    const float* dt_projW = (const float*)d_in[20];
    const float* dt_projb = (const float*)d_in[21];
    const float* A_log    = (const float*)d_in[22];
    const float* Dskip    = (const float*)d_in[23];
    const float* out_projW= (const float*)d_in[24];
    const float* base_W   = (const float*)d_in[25];
    const float* base_b   = (const float*)d_in[26];
    const float* Wp1      = (const float*)d_in[27];
    const float* bp1      = (const float*)d_in[28];
    const float* Wp2      = (const float*)d_in[29];
    const float* bp2      = (const float*)d_in[30];
    float* out = (float*)d_out;

    static cudaStream_t s1 = nullptr, s2 = nullptr;
    static cudaEvent_t evFork = nullptr, evEnc = nullptr, evCsr = nullptr, evMamba = nullptr;
    if (s1 == nullptr) {
        cudaStreamCreateWithFlags(&s1, cudaStreamNonBlocking);
        cudaStreamCreateWithFlags(&s2, cudaStreamNonBlocking);
        cudaEventCreateWithFlags(&evFork, cudaEventDisableTiming);
        cudaEventCreateWithFlags(&evEnc, cudaEventDisableTiming);
        cudaEventCreateWithFlags(&evCsr, cudaEventDisableTiming);
        cudaEventCreateWithFlags(&evMamba, cudaEventDisableTiming);
    }

    dim3 hwGrid((NN + 63) / 64, 5);
    dim3 pnGrid((NN + 63) / 64, 2);

    // main: node encoder (idx 0), fork
    k_enc<<<512, 256>>>(x, W1n, b1n, W2n, b2n, NN, 0);               // 0
    cudaEventRecord(evFork, 0);

    // s2: edge encoder + mamba chain
    cudaStreamWaitEvent(s2, evFork, 0);
    k_enc<<<2048, 256, 0, s2>>>(e_in, W1e, b1e, W2e, b2e, EE, 1);    // 1
    cudaEventRecord(evEnc, s2);

    // main: hw(all 5) then edge l0 (idx 3 -> ncu sample)
    k_hw<<<hwGrid, 256>>>(gnn_W, gnn_b, 0);                          // 2
    cudaStreamWaitEvent(0, evEnc, 0);
    k_edge<<<EE / 128, 256>>>(src, dst, gnn_W, gnn_b, 0);            // 3 <- profiled

    // s1: CSR build (single event)
    cudaStreamWaitEvent(s1, evFork, 0);
    k_zero_deg<<<(NN + 255) / 256, 256, 0, s1>>>();
    k_hist<<<(EE + 255) / 256, 256, 0, s1>>>(src, dst);
    k_scan<<<1, 1024, 0, s1>>>();
    k_fill<<<(EE + 255) / 256, 256, 0, s1>>>(src, dst);
    k_sortcsr<<<(2 * NN * 32 + 255) / 256, 256, 0, s1>>>();
    cudaEventRecord(evCsr, s1);

    // s2: mamba
    k_rlscanplace<<<1, 256, 0, s2>>>(rl);
    k_mamba<<<1250, 256, 0, s2>>>(reads, rl, in_projW, conv_W, conv_b,
                                  x_projW, dt_projW, dt_projb, A_log, Dskip, out_projW);
    cudaEventRecord(evMamba, s2);

    // main: layer 0 aggregation (needs CSR)
    cudaStreamWaitEvent(0, evCsr, 0);
    k_agg<<<NN / 2, 128>>>(src, dst);

    // layers 1..7: pure single-stream chain, zero events
    for (int l = 1; l < NLAYERS; l++) {
        k_hw<<<hwGrid, 256>>>(gnn_W, gnn_b, l);
        k_edge<<<EE / 128, 256>>>(src, dst, gnn_W, gnn_b, l);
        k_agg<<<NN / 2, 128>>>(src, dst);
    }

    // base add needs mamba result
    cudaStreamWaitEvent(0, evMamba, 0);
    k_base<<<(NN * 64 + 255) / 256, 256>>>(base_W, base_b);
    k_prednode<<<pnGrid, 256>>>(Wp1);
    k_prededge<<<EE / 128, 256>>>(src, dst, Wp1, bp1, Wp2, bp2, out);
}